// round 16
// baseline (speedup 1.0000x reference)
#include <cuda_runtime.h>
#include <math.h>

// Depthwise 5x5 Gaussian blur, separable, barrier-free column streaming.
// One warp = one 32-row x 64-col half-plane strip; lane owns 2 columns.
// Vertical pass first (per-thread rolling 5-row window, prefetch distance 4),
// then horizontal on the vertical sum via +-1 lane shuffles. No smem, no
// syncs. Stores use DEFAULT caching (L2 write-back) so output stays
// L2-resident instead of streaming to DRAM.
// x: [16, 256, 64, 64] f32, sigma: [1] f32.

#define HH 64
#define WW 64
#define TPB 256
#define PD  4            // prefetch distance in rows

__global__ __launch_bounds__(TPB) void gauss5_kernel(const float* __restrict__ x,
                                                     const float* __restrict__ sigma_p,
                                                     float* __restrict__ out)
{
    const int tid  = threadIdx.x;
    const int lane = tid & 31;                       // column pair (cols 2l, 2l+1)
    const int gw   = blockIdx.x * (TPB / 32) + (tid >> 5);
    const int plane = gw >> 1;                       // 0..4095
    const int half  = gw & 1;                        // strip: rows 0-31 or 32-63

    const float2* gin  = reinterpret_cast<const float2*>(x)   + (long)plane * 2048;
    float2*       gout = reinterpret_cast<float2*>(out)       + (long)plane * 2048
                                                              + half * 32 * 32;

    // Gaussian taps (symmetric), center tap folded to 1.
    const float sigma = sigma_p[0];
    const float inv2s2 = 1.0f / (2.0f * sigma * sigma);
    const float g0 = expf(-4.0f * inv2s2);   // |d| = 2
    const float g1 = expf(-1.0f * inv2s2);   // |d| = 1
    const float s1 = 2.0f * (g0 + g1) + 1.0f;
    const float invn = 1.0f / (s1 * s1);
    // fold normalization into the vertical stage
    const float vg0 = g0 * invn;
    const float vg1 = g1 * invn;
    const float vg2 = invn;

    const int row0 = half * 32 - 2;          // input row held by in[0]

    // fully unrolled software pipeline: in[j] holds input row row0+j
    float2 in[36];

    #pragma unroll
    for (int j = 0; j < 5 + PD; j++) {
        int r = row0 + j;
        in[j] = (r >= 0 && r < HH) ? gin[r * 32 + lane] : make_float2(0.f, 0.f);
    }

    #pragma unroll
    for (int rr = 0; rr < 32; rr++) {
        // prefetch row rr + 5 + PD
        if (rr + 5 + PD < 36) {
            int r = row0 + rr + 5 + PD;
            in[rr + 5 + PD] = (r >= 0 && r < HH) ? gin[r * 32 + lane]
                                                 : make_float2(0.f, 0.f);
        }

        // vertical pass on rows rr-2 .. rr+2 (normalization folded in)
        float2 v;
        v.x = vg0 * (in[rr].x + in[rr+4].x) + vg1 * (in[rr+1].x + in[rr+3].x)
            + vg2 * in[rr+2].x;
        v.y = vg0 * (in[rr].y + in[rr+4].y) + vg1 * (in[rr+1].y + in[rr+3].y)
            + vg2 * in[rr+2].y;

        // horizontal pass on the vertical sum (in-warp shuffles)
        float px = __shfl_up_sync(0xffffffffu, v.x, 1);    // col 2l-2
        float py = __shfl_up_sync(0xffffffffu, v.y, 1);    // col 2l-1
        float nx = __shfl_down_sync(0xffffffffu, v.x, 1);  // col 2l+2
        float ny = __shfl_down_sync(0xffffffffu, v.y, 1);  // col 2l+3
        if (lane == 0)  { px = 0.0f; py = 0.0f; }          // left zero-pad
        if (lane == 31) { nx = 0.0f; ny = 0.0f; }          // right zero-pad

        float2 o;
        o.x = g0 * (px + nx) + g1 * (py + v.y) + v.x;
        o.y = g0 * (py + ny) + g1 * (v.x + nx) + v.y;
        gout[rr * 32 + lane] = o;            // default caching: L2 write-back
    }
}

extern "C" void kernel_launch(void* const* d_in, const int* in_sizes, int n_in,
                              void* d_out, int out_size) {
    const float* x = (const float*)d_in[0];
    const float* sigma = (const float*)d_in[1];
    float* out = (float*)d_out;
    int planes = in_sizes[0] / (HH * WW);            // 4096
    int warps  = planes * 2;                         // half-plane strips
    gauss5_kernel<<<warps / (TPB / 32), TPB>>>(x, sigma, out);
}